// round 1
// baseline (speedup 1.0000x reference)
#include <cuda_runtime.h>
#include <cuda_bf16.h>

// Problem constants (fixed by the benchmark instance)
#define L_TOK  8192
#define C_DIM  1024
#define INNER  1024
#define H_NUM  16
#define D_DIM  64
#define NSHIFT 16

// Scratch (allocation-free rule: __device__ globals)
__device__ float g_q[L_TOK * INNER];
__device__ float g_k[L_TOK * INNER];
__device__ float g_v[L_TOK * INNER];
__device__ float g_att[L_TOK * INNER];

// 12 spatial shifts then 4 temporal shifts (reference order)
__constant__ int c_shift[NSHIFT] = {1,-1,2,-2,4,-4,8,-8,16,-16,32,-32, 1,-1,2,-2};

// ---------------------------------------------------------------------------
// SGEMM: C[M,N] = A[M,K] @ B[K,N] + bias[N]   (row-major, fp32)
// 128x128 tile, BK=16, 256 threads, 8x8 micro-tile
// ---------------------------------------------------------------------------
__global__ __launch_bounds__(256, 2)
void sgemm_bias(const float* __restrict__ A, const float* __restrict__ B,
                const float* __restrict__ bias, float* __restrict__ C,
                int M, int N, int K)
{
    const int BM = 128, BN = 128, BK = 16;
    __shared__ float As[BK][BM];
    __shared__ float Bs[BK][BN];

    const int tid = threadIdx.x;
    const int bm = blockIdx.y * BM;
    const int bn = blockIdx.x * BN;
    const int ty = tid >> 4;     // 0..15
    const int tx = tid & 15;     // 0..15

    float acc[8][8] = {};

    for (int k0 = 0; k0 < K; k0 += BK) {
        // Load A tile 128x16 (2 float4 per thread), store transposed As[k][m]
        #pragma unroll
        for (int i = 0; i < 2; i++) {
            int v = tid + i * 256;          // 0..511
            int row = v >> 2;               // 0..127
            int c4  = (v & 3) * 4;          // 0,4,8,12
            float4 a = *(const float4*)&A[(size_t)(bm + row) * K + k0 + c4];
            As[c4 + 0][row] = a.x;
            As[c4 + 1][row] = a.y;
            As[c4 + 2][row] = a.z;
            As[c4 + 3][row] = a.w;
        }
        // Load B tile 16x128 (2 float4 per thread)
        #pragma unroll
        for (int i = 0; i < 2; i++) {
            int v = tid + i * 256;
            int row = v >> 5;               // 0..15
            int c4  = (v & 31) * 4;         // 0..124
            *(float4*)&Bs[row][c4] = *(const float4*)&B[(size_t)(k0 + row) * N + bn + c4];
        }
        __syncthreads();

        #pragma unroll
        for (int kk = 0; kk < BK; kk++) {
            float a[8], b[8];
            float4 a0 = *(const float4*)&As[kk][ty * 8];
            float4 a1 = *(const float4*)&As[kk][ty * 8 + 4];
            float4 b0 = *(const float4*)&Bs[kk][tx * 8];
            float4 b1 = *(const float4*)&Bs[kk][tx * 8 + 4];
            a[0]=a0.x; a[1]=a0.y; a[2]=a0.z; a[3]=a0.w;
            a[4]=a1.x; a[5]=a1.y; a[6]=a1.z; a[7]=a1.w;
            b[0]=b0.x; b[1]=b0.y; b[2]=b0.z; b[3]=b0.w;
            b[4]=b1.x; b[5]=b1.y; b[6]=b1.z; b[7]=b1.w;
            #pragma unroll
            for (int i = 0; i < 8; i++)
                #pragma unroll
                for (int j = 0; j < 8; j++)
                    acc[i][j] += a[i] * b[j];
        }
        __syncthreads();
    }

    #pragma unroll
    for (int i = 0; i < 8; i++) {
        int row = bm + ty * 8 + i;
        #pragma unroll
        for (int j = 0; j < 8; j += 4) {
            int col = bn + tx * 8 + j;
            float4 o;
            o.x = acc[i][j + 0] + bias[col + 0];
            o.y = acc[i][j + 1] + bias[col + 1];
            o.z = acc[i][j + 2] + bias[col + 2];
            o.w = acc[i][j + 3] + bias[col + 3];
            *(float4*)&C[(size_t)row * N + col] = o;
        }
    }
}

// ---------------------------------------------------------------------------
// RMS norm in-place over the last dim (INNER), then multiply by weight
// One block (256 threads) per row
// ---------------------------------------------------------------------------
__global__ __launch_bounds__(256)
void rms_kernel(float* __restrict__ Y, const float* __restrict__ w)
{
    const int row = blockIdx.x;
    float* y = Y + (size_t)row * INNER;

    float ss = 0.f;
    for (int i = threadIdx.x; i < INNER; i += 256) {
        float t = y[i];
        ss += t * t;
    }
    #pragma unroll
    for (int o = 16; o; o >>= 1) ss += __shfl_xor_sync(0xffffffffu, ss, o);

    __shared__ float red[8];
    if ((threadIdx.x & 31) == 0) red[threadIdx.x >> 5] = ss;
    __syncthreads();
    if (threadIdx.x == 0) {
        float tot = 0.f;
        #pragma unroll
        for (int i = 0; i < 8; i++) tot += red[i];
        red[0] = rsqrtf(tot * (1.0f / INNER) + 1e-6f);
    }
    __syncthreads();
    float r = red[0];
    for (int i = threadIdx.x; i < INNER; i += 256)
        y[i] = y[i] * r * w[i];
}

// ---------------------------------------------------------------------------
// Small-world attention: one warp per (token, head).
// Lane l owns dims {l, l+32} of D=64.
// ---------------------------------------------------------------------------
__global__ __launch_bounds__(256)
void attn_kernel(const float* __restrict__ q, const float* __restrict__ k,
                 const float* __restrict__ v, const float* __restrict__ eb,
                 const int* __restrict__ p_nf, float* __restrict__ out)
{
    const int gwarp = (blockIdx.x * blockDim.x + threadIdx.x) >> 5;
    const int lane  = threadIdx.x & 31;
    const int token = gwarp >> 4;     // / H_NUM
    const int head  = gwarp & 15;

    // num_frames may arrive as int32 or float32 bits; disambiguate.
    int iv = *p_nf;
    int T;
    if (iv >= 1 && iv <= L_TOK && (L_TOK % iv) == 0) T = iv;
    else T = (int)__int_as_float(iv);
    const int S = L_TOK / T;

    const int t = token / S;
    const int s = token - t * S;
    const int qb = token * INNER + head * D_DIM;

    const float q0 = q[qb + lane];
    const float q1 = q[qb + 32 + lane];

    float sc[NSHIFT], v0r[NSHIFT], v1r[NSHIFT];

    #pragma unroll
    for (int n = 0; n < NSHIFT; n++) {
        int sft = c_shift[n];
        int tok2;
        if (n < 12) {
            int s2 = s + sft;
            while (s2 < 0)   s2 += S;
            while (s2 >= S)  s2 -= S;
            tok2 = t * S + s2;
        } else {
            int t2 = t + sft;
            while (t2 < 0)   t2 += T;
            while (t2 >= T)  t2 -= T;
            tok2 = t2 * S + s;
        }
        int nb = tok2 * INNER + head * D_DIM;
        float p = q0 * k[nb + lane] + q1 * k[nb + 32 + lane];
        #pragma unroll
        for (int o = 16; o; o >>= 1) p += __shfl_xor_sync(0xffffffffu, p, o);
        sc[n]  = p * 0.125f + eb[head * NSHIFT + n];   // scale = D^-0.5 = 0.125
        v0r[n] = v[nb + lane];
        v1r[n] = v[nb + 32 + lane];
    }

    // softmax over 16 shifts
    float m = sc[0];
    #pragma unroll
    for (int n = 1; n < NSHIFT; n++) m = fmaxf(m, sc[n]);
    float sum = 0.f;
    #pragma unroll
    for (int n = 0; n < NSHIFT; n++) { sc[n] = __expf(sc[n] - m); sum += sc[n]; }
    float inv = 1.0f / sum;

    float a0 = 0.f, a1 = 0.f;
    #pragma unroll
    for (int n = 0; n < NSHIFT; n++) {
        float w = sc[n] * inv;
        a0 += w * v0r[n];
        a1 += w * v1r[n];
    }
    out[qb + lane]      = a0;
    out[qb + 32 + lane] = a1;
}

// ---------------------------------------------------------------------------
extern "C" void kernel_launch(void* const* d_in, const int* in_sizes, int n_in,
                              void* d_out, int out_size)
{
    const float* x  = (const float*)d_in[0];
    const float* Wq = (const float*)d_in[1];
    const float* bq = (const float*)d_in[2];
    const float* Wk = (const float*)d_in[3];
    const float* bk = (const float*)d_in[4];
    const float* Wv = (const float*)d_in[5];
    const float* bv = (const float*)d_in[6];
    const float* qn = (const float*)d_in[7];
    const float* kn = (const float*)d_in[8];
    const float* eb = (const float*)d_in[9];
    const float* Wo = (const float*)d_in[10];
    const float* bo = (const float*)d_in[11];
    const int*   nf = (const int*)d_in[12];
    float* out = (float*)d_out;

    float *q, *k, *v, *att;
    cudaGetSymbolAddress((void**)&q,   g_q);
    cudaGetSymbolAddress((void**)&k,   g_k);
    cudaGetSymbolAddress((void**)&v,   g_v);
    cudaGetSymbolAddress((void**)&att, g_att);

    dim3 ggrid(INNER / 128, L_TOK / 128);   // (8, 64)
    dim3 gblk(256);

    // QKV projections
    sgemm_bias<<<ggrid, gblk>>>(x, Wq, bq, q, L_TOK, INNER, C_DIM);
    sgemm_bias<<<ggrid, gblk>>>(x, Wk, bk, k, L_TOK, INNER, C_DIM);
    sgemm_bias<<<ggrid, gblk>>>(x, Wv, bv, v, L_TOK, INNER, C_DIM);

    // RMS norms (over full inner dim, before head split)
    rms_kernel<<<L_TOK, 256>>>(q, qn);
    rms_kernel<<<L_TOK, 256>>>(k, kn);

    // Attention: 8192 tokens * 16 heads = 131072 warps, 8 warps/block
    attn_kernel<<<(L_TOK * H_NUM) / 8, 256>>>(q, k, v, eb, nf, att);

    // Output projection
    dim3 ogrid(C_DIM / 128, L_TOK / 128);
    sgemm_bias<<<ogrid, gblk>>>(att, Wo, bo, out, L_TOK, C_DIM, INNER);
}

// round 3
// speedup vs baseline: 2.2656x; 2.2656x over previous
#include <cuda_runtime.h>
#include <cuda_bf16.h>
#include <cstdint>

#define L_TOK  8192
#define C_DIM  1024
#define INNER  1024
#define H_NUM  16
#define D_DIM  64
#define NSHIFT 16

#define BM 128
#define BN 128
#define BK 64
#define NSTAGE 3
#define STAGE_BYTES 65536          // Ahi 16K | Alo 16K | Bhi 16K | Blo 16K
#define SMEM_TOTAL (NSTAGE * STAGE_BYTES)

// ---------------- scratch (__device__ globals; no allocs allowed) -----------
__device__ __align__(256) unsigned short g_xhi [L_TOK * 1024];
__device__ __align__(256) unsigned short g_xlo [L_TOK * 1024];
__device__ __align__(256) unsigned short g_ahi [L_TOK * 1024];
__device__ __align__(256) unsigned short g_alo [L_TOK * 1024];
__device__ __align__(256) unsigned short g_wqkvhi[3072 * 1024];   // [n][k]
__device__ __align__(256) unsigned short g_wqkvlo[3072 * 1024];
__device__ __align__(256) unsigned short g_wohi[1024 * 1024];
__device__ __align__(256) unsigned short g_wolo[1024 * 1024];
__device__ float g_bqkv[3072];
__device__ float g_q[L_TOK * INNER];
__device__ float g_k[L_TOK * INNER];
__device__ float g_v[L_TOK * INNER];

__constant__ int c_shift[NSHIFT] = {1,-1,2,-2,4,-4,8,-8,16,-16,32,-32, 1,-1,2,-2};

// ---------------- helpers ---------------------------------------------------
__device__ __forceinline__ uint32_t smem_u32(const void* p){
    uint32_t a;
    asm("{ .reg .u64 t; cvta.to.shared.u64 t, %1; cvt.u32.u64 %0, t; }" : "=r"(a) : "l"(p));
    return a;
}
__device__ __forceinline__ void split_pair(float a, float b, uint32_t& hi, uint32_t& lo){
    __nv_bfloat16 h0 = __float2bfloat16(a), h1 = __float2bfloat16(b);
    float r0 = a - __bfloat162float(h0), r1 = b - __bfloat162float(h1);
    __nv_bfloat16 l0 = __float2bfloat16(r0), l1 = __float2bfloat16(r1);
    hi = (uint32_t)__bfloat16_as_ushort(h0) | ((uint32_t)__bfloat16_as_ushort(h1) << 16);
    lo = (uint32_t)__bfloat16_as_ushort(l0) | ((uint32_t)__bfloat16_as_ushort(l1) << 16);
}
__device__ __forceinline__ void cp16(uint32_t s, const void* g){
    asm volatile("cp.async.cg.shared.global [%0], [%1], 16;" :: "r"(s), "l"(g) : "memory");
}
__device__ __forceinline__ void ldsm_x4(uint32_t* r, uint32_t addr){
    asm volatile("ldmatrix.sync.aligned.m8n8.x4.shared.b16 {%0,%1,%2,%3}, [%4];"
        : "=r"(r[0]), "=r"(r[1]), "=r"(r[2]), "=r"(r[3]) : "r"(addr));
}
__device__ __forceinline__ void mma16816(float* d, const uint32_t* a, uint32_t b0, uint32_t b1){
    asm volatile("mma.sync.aligned.m16n8k16.row.col.f32.bf16.bf16.f32 "
        "{%0,%1,%2,%3}, {%4,%5,%6,%7}, {%8,%9}, {%0,%1,%2,%3};"
        : "+f"(d[0]), "+f"(d[1]), "+f"(d[2]), "+f"(d[3])
        : "r"(a[0]), "r"(a[1]), "r"(a[2]), "r"(a[3]), "r"(b0), "r"(b1));
}

// ---------------- converters -------------------------------------------------
// x fp32 row-major -> bf16 hi/lo row-major [8192][1024]
__global__ __launch_bounds__(256)
void conv_x(const float* __restrict__ x, uint32_t* __restrict__ hi, uint32_t* __restrict__ lo)
{
    int gid = blockIdx.x * 256 + threadIdx.x;      // over 4M float2
    float2 f = ((const float2*)x)[gid];
    uint32_t h, l;
    split_pair(f.x, f.y, h, l);
    hi[gid] = h;
    lo[gid] = l;
}

// W [K=1024][N=1024] fp32 -> W^T bf16 hi/lo [n][k] (n offset for qkv concat)
__global__ __launch_bounds__(256)
void conv_w(const float* __restrict__ W, uint32_t* __restrict__ hi, uint32_t* __restrict__ lo,
            int n_off)
{
    __shared__ float tile[32][33];
    const int t = threadIdx.x;
    const int tx = t & 31, ty = t >> 5;     // 32 x 8
    const int k0 = blockIdx.x * 32, n0 = blockIdx.y * 32;
    #pragma unroll
    for (int r = 0; r < 4; r++) {
        int kl = ty + r * 8;
        tile[kl][tx] = W[(size_t)(k0 + kl) * 1024 + n0 + tx];
    }
    __syncthreads();
    #pragma unroll
    for (int w = 0; w < 2; w++) {
        int oid = t * 2 + w;                // 0..511
        int j = oid >> 4;                   // n row 0..31
        int u = oid & 15;                   // k u32 0..15
        uint32_t h, l;
        split_pair(tile[2*u][j], tile[2*u+1][j], h, l);
        size_t idx = (size_t)(n_off + n0 + j) * 512 + (k0 >> 1) + u;
        hi[idx] = h;
        lo[idx] = l;
    }
}

__global__ void bias_cat(const float* bq, const float* bk, const float* bv, float* dst)
{
    int i = blockIdx.x * 256 + threadIdx.x;
    if (i < 1024)      dst[i] = bq[i];
    else if (i < 2048) dst[i] = bk[i - 1024];
    else if (i < 3072) dst[i] = bv[i - 2048];
}

// ---------------- bf16-split HMMA GEMM --------------------------------------
// C[M, Ntot] = A[M,1024] @ B^T  (B packed [n][k]) + bias
// mode 0: Ntot=3072, outputs split into out0/out1/out2 (1024 each). mode 1: single.
__global__ __launch_bounds__(256, 1)
void gemm_mma(const unsigned short* __restrict__ Ahi, const unsigned short* __restrict__ Alo,
              const unsigned short* __restrict__ Bhi, const unsigned short* __restrict__ Blo,
              const float* __restrict__ bias,
              float* __restrict__ out0, float* __restrict__ out1, float* __restrict__ out2,
              int mode)
{
    extern __shared__ __align__(128) unsigned char smem[];
    const uint32_t sbase = smem_u32(smem);
    const int tid  = threadIdx.x;
    const int lane = tid & 31;
    const int wid  = tid >> 5;
    const int wm   = wid >> 2;         // 0..1
    const int wn   = wid & 3;          // 0..3
    const int mblk = blockIdx.y * BM;
    const int nblk = blockIdx.x * BN;

    // stage loader: 4 matrices x 128 rows x 8 chunks(16B)
    auto load_stage = [&](int kc, int st){
        const uint32_t sb = sbase + st * STAGE_BYTES;
        #pragma unroll
        for (int mat = 0; mat < 4; mat++) {
            const unsigned short* gsrc;
            int rbase;
            if (mat == 0)      { gsrc = Ahi; rbase = mblk; }
            else if (mat == 1) { gsrc = Alo; rbase = mblk; }
            else if (mat == 2) { gsrc = Bhi; rbase = nblk; }
            else               { gsrc = Blo; rbase = nblk; }
            #pragma unroll
            for (int j = 0; j < 4; j++) {
                int id  = tid + j * 256;        // 0..1023
                int row = id >> 3;
                int c   = id & 7;
                uint32_t soff = mat * 16384 + row * 128 + ((c ^ (row & 7)) << 4);
                const void* g = gsrc + (size_t)(rbase + row) * 1024 + kc * 64 + c * 8;
                cp16(sb + soff, g);
            }
        }
        asm volatile("cp.async.commit_group;" ::: "memory");
    };

    float acc[4][4][4];
    #pragma unroll
    for (int i = 0; i < 4; i++)
        #pragma unroll
        for (int j = 0; j < 4; j++)
            #pragma unroll
            for (int e = 0; e < 4; e++) acc[i][j][e] = 0.f;

    load_stage(0, 0);
    load_stage(1, 1);

    for (int kc = 0; kc < 16; kc++) {
        if (kc < 15) asm volatile("cp.async.wait_group 1;" ::: "memory");
        else         asm volatile("cp.async.wait_group 0;" ::: "memory");
        __syncthreads();

        const uint32_t sb = sbase + (kc % NSTAGE) * STAGE_BYTES;
        const uint32_t sAhi = sb, sAlo = sb + 16384, sBhi = sb + 32768, sBlo = sb + 49152;

        #pragma unroll
        for (int s = 0; s < 4; s++) {
            // A fragments: 4 m-tiles, hi+lo
            uint32_t ah[4][4], al[4][4];
            {
                int r = wm * 64 + (lane & 15);
                int c = 2 * s + (lane >> 4);
                #pragma unroll
                for (int mt = 0; mt < 4; mt++) {
                    int rr = r + mt * 16;
                    uint32_t off = rr * 128 + ((c ^ (rr & 7)) << 4);
                    ldsm_x4(ah[mt], sAhi + off);
                    ldsm_x4(al[mt], sAlo + off);
                }
            }
            // B fragments: 4 n-tiles (two x4 loads cover 2 tiles each), hi+lo
            uint32_t bh[4][2], bl[4][2];
            {
                int r = wn * 32 + (lane & 15);
                int c = 2 * s + (lane >> 4);
                #pragma unroll
                for (int p = 0; p < 2; p++) {
                    int rr = r + p * 16;
                    uint32_t off = rr * 128 + ((c ^ (rr & 7)) << 4);
                    uint32_t t4[4];
                    ldsm_x4(t4, sBhi + off);
                    bh[p*2+0][0] = t4[0]; bh[p*2+0][1] = t4[2];
                    bh[p*2+1][0] = t4[1]; bh[p*2+1][1] = t4[3];
                    ldsm_x4(t4, sBlo + off);
                    bl[p*2+0][0] = t4[0]; bl[p*2+0][1] = t4[2];
                    bl[p*2+1][0] = t4[1]; bl[p*2+1][1] = t4[3];
                }
            }
            #pragma unroll
            for (int mt = 0; mt < 4; mt++)
                #pragma unroll
                for (int nt = 0; nt < 4; nt++) {
                    mma16816(acc[mt][nt], ah[mt], bh[nt][0], bh[nt][1]);
                    mma16816(acc[mt][nt], ah[mt], bl[nt][0], bl[nt][1]);
                    mma16816(acc[mt][nt], al[mt], bh[nt][0], bh[nt][1]);
                }
        }
        __syncthreads();
        if (kc + 2 < 16) load_stage(kc + 2, (kc + 2) % NSTAGE);
    }

    // epilogue
    #pragma unroll
    for (int mt = 0; mt < 4; mt++) {
        #pragma unroll
        for (int nt = 0; nt < 4; nt++) {
            int m0  = mblk + wm * 64 + mt * 16 + (lane >> 2);
            int n_g = nblk + wn * 32 + nt * 8 + 2 * (lane & 3);
            float* dst; int nl;
            if (mode == 0) {
                int bi = n_g >> 10;
                dst = (bi == 0) ? out0 : (bi == 1) ? out1 : out2;
                nl = n_g & 1023;
            } else { dst = out0; nl = n_g; }
            float b0 = bias[n_g], b1 = bias[n_g + 1];
            float2 v0 = make_float2(acc[mt][nt][0] + b0, acc[mt][nt][1] + b1);
            float2 v1 = make_float2(acc[mt][nt][2] + b0, acc[mt][nt][3] + b1);
            *(float2*)&dst[(size_t)m0 * 1024 + nl] = v0;
            *(float2*)&dst[(size_t)(m0 + 8) * 1024 + nl] = v1;
        }
    }
}

// ---------------- RMS norm ---------------------------------------------------
__global__ __launch_bounds__(256)
void rms_kernel(float* __restrict__ Y, const float* __restrict__ w)
{
    const int row = blockIdx.x;
    float* y = Y + (size_t)row * INNER;
    float ss = 0.f;
    for (int i = threadIdx.x; i < INNER; i += 256) { float t = y[i]; ss += t * t; }
    #pragma unroll
    for (int o = 16; o; o >>= 1) ss += __shfl_xor_sync(0xffffffffu, ss, o);
    __shared__ float red[8];
    if ((threadIdx.x & 31) == 0) red[threadIdx.x >> 5] = ss;
    __syncthreads();
    if (threadIdx.x == 0) {
        float tot = 0.f;
        #pragma unroll
        for (int i = 0; i < 8; i++) tot += red[i];
        red[0] = rsqrtf(tot * (1.0f / INNER) + 1e-6f);
    }
    __syncthreads();
    float r = red[0];
    for (int i = threadIdx.x; i < INNER; i += 256) y[i] = y[i] * r * w[i];
}

// ---------------- small-world attention -------------------------------------
// one warp per (token, head); lane owns dims {2l,2l+1}; writes packed bf16 hi/lo
__global__ __launch_bounds__(256)
void attn_kernel(const float* __restrict__ q, const float* __restrict__ k,
                 const float* __restrict__ v, const float* __restrict__ eb,
                 const int* __restrict__ p_nf,
                 uint32_t* __restrict__ ahi, uint32_t* __restrict__ alo)
{
    const int gwarp = (blockIdx.x * blockDim.x + threadIdx.x) >> 5;
    const int lane  = threadIdx.x & 31;
    const int token = gwarp >> 4;
    const int head  = gwarp & 15;

    int iv = *p_nf;
    int T;
    if (iv >= 1 && iv <= L_TOK && (L_TOK % iv) == 0) T = iv;
    else T = (int)__int_as_float(iv);
    const int S = L_TOK / T;

    const int t = token / S;
    const int s = token - t * S;
    const int qb = token * INNER + head * D_DIM;

    float2 qv = *(const float2*)&q[qb + 2 * lane];

    float sc[NSHIFT], va[NSHIFT], vb[NSHIFT];
    #pragma unroll
    for (int n = 0; n < NSHIFT; n++) {
        int sft = c_shift[n];
        int tok2;
        if (n < 12) {
            int s2 = s + sft;
            while (s2 < 0)  s2 += S;
            while (s2 >= S) s2 -= S;
            tok2 = t * S + s2;
        } else {
            int t2 = t + sft;
            while (t2 < 0)  t2 += T;
            while (t2 >= T) t2 -= T;
            tok2 = t2 * S + s;
        }
        int nb = tok2 * INNER + head * D_DIM;
        float2 kv = *(const float2*)&k[nb + 2 * lane];
        float p = qv.x * kv.x + qv.y * kv.y;
        #pragma unroll
        for (int o = 16; o; o >>= 1) p += __shfl_xor_sync(0xffffffffu, p, o);
        sc[n] = p * 0.125f + eb[head * NSHIFT + n];
        float2 vv = *(const float2*)&v[nb + 2 * lane];
        va[n] = vv.x; vb[n] = vv.y;
    }

    float m = sc[0];
    #pragma unroll
    for (int n = 1; n < NSHIFT; n++) m = fmaxf(m, sc[n]);
    float sum = 0.f;
    #pragma unroll
    for (int n = 0; n < NSHIFT; n++) { sc[n] = __expf(sc[n] - m); sum += sc[n]; }
    float inv = 1.0f / sum;

    float a0 = 0.f, a1 = 0.f;
    #pragma unroll
    for (int n = 0; n < NSHIFT; n++) {
        float w = sc[n] * inv;
        a0 += w * va[n];
        a1 += w * vb[n];
    }

    uint32_t h, l;
    split_pair(a0, a1, h, l);
    uint32_t idx = (uint32_t)token * 512 + head * 32 + lane;
    ahi[idx] = h;
    alo[idx] = l;
}

// ---------------------------------------------------------------------------
extern "C" void kernel_launch(void* const* d_in, const int* in_sizes, int n_in,
                              void* d_out, int out_size)
{
    const float* x  = (const float*)d_in[0];
    const float* Wq = (const float*)d_in[1];
    const float* bq = (const float*)d_in[2];
    const float* Wk = (const float*)d_in[3];
    const float* bk = (const float*)d_in[4];
    const float* Wv = (const float*)d_in[5];
    const float* bv = (const float*)d_in[6];
    const float* qn = (const float*)d_in[7];
    const float* kn = (const float*)d_in[8];
    const float* eb = (const float*)d_in[9];
    const float* Wo = (const float*)d_in[10];
    const float* bo = (const float*)d_in[11];
    const int*   nf = (const int*)d_in[12];
    float* out = (float*)d_out;

    unsigned short *xhi,*xlo,*ahi,*alo,*wqh,*wql,*woh,*wol;
    float *bqkv,*q,*k,*v;
    cudaGetSymbolAddress((void**)&xhi, g_xhi);
    cudaGetSymbolAddress((void**)&xlo, g_xlo);
    cudaGetSymbolAddress((void**)&ahi, g_ahi);
    cudaGetSymbolAddress((void**)&alo, g_alo);
    cudaGetSymbolAddress((void**)&wqh, g_wqkvhi);
    cudaGetSymbolAddress((void**)&wql, g_wqkvlo);
    cudaGetSymbolAddress((void**)&woh, g_wohi);
    cudaGetSymbolAddress((void**)&wol, g_wolo);
    cudaGetSymbolAddress((void**)&bqkv, g_bqkv);
    cudaGetSymbolAddress((void**)&q, g_q);
    cudaGetSymbolAddress((void**)&k, g_k);
    cudaGetSymbolAddress((void**)&v, g_v);

    cudaFuncSetAttribute(gemm_mma, cudaFuncAttributeMaxDynamicSharedMemorySize, SMEM_TOTAL);

    // pack inputs to bf16 hi/lo
    conv_x<<<16384, 256>>>(x, (uint32_t*)xhi, (uint32_t*)xlo);
    conv_w<<<dim3(32, 32), 256>>>(Wq, (uint32_t*)wqh, (uint32_t*)wql, 0);
    conv_w<<<dim3(32, 32), 256>>>(Wk, (uint32_t*)wqh, (uint32_t*)wql, 1024);
    conv_w<<<dim3(32, 32), 256>>>(Wv, (uint32_t*)wqh, (uint32_t*)wql, 2048);
    conv_w<<<dim3(32, 32), 256>>>(Wo, (uint32_t*)woh, (uint32_t*)wol, 0);
    bias_cat<<<12, 256>>>(bq, bk, bv, bqkv);

    // fused QKV projection (N = 3072)
    gemm_mma<<<dim3(24, 64), 256, SMEM_TOTAL>>>(xhi, xlo, wqh, wql, bqkv, q, k, v, 0);

    rms_kernel<<<L_TOK, 256>>>(q, qn);
    rms_kernel<<<L_TOK, 256>>>(k, kn);

    attn_kernel<<<(L_TOK * H_NUM) / 8, 256>>>(q, k, v, eb, nf,
                                              (uint32_t*)ahi, (uint32_t*)alo);

    // output projection
    gemm_mma<<<dim3(8, 64), 256, SMEM_TOTAL>>>(ahi, alo, woh, wol, bo, out, out, out, 1);
}